// round 1
// baseline (speedup 1.0000x reference)
#include <cuda_runtime.h>
#include <math.h>

// ---------------- problem constants ----------------
#define TOK   2048        // B*S tokens
#define HDIM  1024        // hidden
#define NE    8           // routed experts
#define IDIM  512         // routed expert intermediate
#define SIDIM 1024        // shared expert intermediate
#define RMAX  4608        // TOK*2 + NE*64 (64-aligned expert segments)

// ---------------- device scratch (no allocations allowed) ----------------
__device__ int   g_topi[TOK][2];
__device__ float g_topw[TOK][2];
__device__ float g_wsum[NE];
__device__ float g_wmean[NE];
__device__ int   g_cnt[NE];
__device__ int   g_off[NE + 1];
__device__ int   g_fill[NE];
__device__ int   g_pairtok[RMAX];     // token index or -1 (dummy pad row)
__device__ int   g_rowexp[RMAX];      // expert id of row's segment
__device__ int   g_pairof[TOK][2];    // token -> its two rows
__device__ __align__(16) float g_hbuf[RMAX][IDIM];    // routed silu(g)*u
__device__ __align__(16) float g_ybuf[RMAX][HDIM];    // routed down-proj
__device__ __align__(16) float g_hsbuf[TOK][SIDIM];   // shared silu(g)*u

// ---------------- 1) router: logits, sigmoid, top-2, normalize ----------------
__global__ __launch_bounds__(256) void router_kernel(const float* __restrict__ x,
                                                     const float* __restrict__ gw,
                                                     const float* __restrict__ lb)
{
    int tid  = threadIdx.x;
    int lane = tid & 31;
    int t    = blockIdx.x * 8 + (tid >> 5);
    if (t >= TOK) return;
    const float* xr = x + (long)t * HDIM;

    float acc[NE];
#pragma unroll
    for (int e = 0; e < NE; e++) acc[e] = 0.f;

    for (int j = lane; j < HDIM; j += 32) {
        float xv = xr[j];
#pragma unroll
        for (int e = 0; e < NE; e++) acc[e] += xv * gw[e * HDIM + j];
    }
#pragma unroll
    for (int e = 0; e < NE; e++) {
#pragma unroll
        for (int o = 16; o > 0; o >>= 1) acc[e] += __shfl_xor_sync(0xffffffffu, acc[e], o);
    }
    if (lane == 0) {
        float sc[NE];
#pragma unroll
        for (int e = 0; e < NE; e++) sc[e] = 1.f / (1.f + expf(-(acc[e] + lb[e])));
        // top-2, ties -> lower index (matches jax top_k)
        int i0 = 0;
#pragma unroll
        for (int e = 1; e < NE; e++) if (sc[e] > sc[i0]) i0 = e;
        int i1 = -1;
#pragma unroll
        for (int e = 0; e < NE; e++) {
            if (e == i0) continue;
            if (i1 < 0 || sc[e] > sc[i1]) i1 = e;
        }
        float w0 = sc[i0], w1 = sc[i1];
        float s  = w0 + w1 + 1e-8f;
        g_topi[t][0] = i0; g_topi[t][1] = i1;
        g_topw[t][0] = w0 / s; g_topw[t][1] = w1 / s;
    }
}

// ---------------- 2) per-expert wsum/count (deterministic tree) ----------------
__global__ __launch_bounds__(256) void stats_kernel()
{
    int e   = blockIdx.x;
    int tid = threadIdx.x;
    float ws = 0.f;
    int   c  = 0;
    for (int t = tid; t < TOK; t += 256) {
#pragma unroll
        for (int k = 0; k < 2; k++) {
            if (g_topi[t][k] == e) { ws += g_topw[t][k]; c++; }
        }
    }
    __shared__ float sw[256];
    __shared__ int   sc[256];
    sw[tid] = ws; sc[tid] = c;
    __syncthreads();
    for (int s = 128; s > 0; s >>= 1) {
        if (tid < s) { sw[tid] += sw[tid + s]; sc[tid] += sc[tid + s]; }
        __syncthreads();
    }
    if (tid == 0) { g_wsum[e] = sw[0]; g_cnt[e] = sc[0]; }
}

// ---------------- 3) prefix: 64-aligned segment offsets, wmean, reset fill ----
__global__ void prefix_kernel()
{
    g_off[0] = 0;
    for (int e = 0; e < NE; e++) {
        int c = g_cnt[e];
        int cm = c > 1 ? c : 1;
        g_wmean[e] = g_wsum[e] / (float)cm;
        g_fill[e]  = 0;
        g_off[e + 1] = g_off[e] + ((c + 63) & ~63);
    }
}

// ---------------- 4) row metadata: init pads, expert per row ------------------
__global__ __launch_bounds__(256) void rowmeta_kernel()
{
    int r = blockIdx.x * 256 + threadIdx.x;
    if (r >= RMAX) return;
    g_pairtok[r] = -1;
    int e = NE - 1;
#pragma unroll
    for (int i = 0; i < NE; i++) {
        if (r < g_off[i + 1]) { e = i; break; }
    }
    g_rowexp[r] = e;
}

// ---------------- 5) scatter tokens into expert segments ----------------------
__global__ __launch_bounds__(256) void build_kernel()
{
    int t = blockIdx.x * 256 + threadIdx.x;
    if (t >= TOK) return;
#pragma unroll
    for (int k = 0; k < 2; k++) {
        int e   = g_topi[t][k];
        int pos = atomicAdd(&g_fill[e], 1);
        int r   = g_off[e] + pos;
        g_pairtok[r]  = t;
        g_pairof[t][k] = r;
    }
}

// ---------------- fused gate+up+silu GEMM (64x64x16 tiles) --------------------
// ROUTED: A = x gathered via pairtok, W per expert, C = g_hbuf (ld IDIM)
// !ROUTED: A = x rows direct,        W shared,     C = g_hsbuf (ld SIDIM)
template <bool ROUTED>
__global__ __launch_bounds__(256) void gateup_kernel(const float* __restrict__ A,
                                                     const float* __restrict__ Wg,
                                                     const float* __restrict__ Wu)
{
    __shared__ float As[16][68];
    __shared__ float Bg[16][68];
    __shared__ float Bu[16][68];
    __shared__ int   stok[64];

    constexpr int KD  = HDIM;
    constexpr int LDC = ROUTED ? IDIM : SIDIM;
    float* C = ROUTED ? &g_hbuf[0][0] : &g_hsbuf[0][0];

    int tid = threadIdx.x;
    int r0  = blockIdx.y * 64;
    int n0  = blockIdx.x * 64;

    int e = 0;
    if (ROUTED) {
        if (tid < 64) stok[tid] = g_pairtok[r0 + tid];
        __syncthreads();
        if (stok[0] < 0) return;          // fully-dummy block (segments 64-aligned)
        e = g_rowexp[r0];
    }
    const float* wg = Wg + (long)e * IDIM * HDIM;
    const float* wu = Wu + (long)e * IDIM * HDIM;

    int lrow = tid >> 2;
    int kq   = (tid & 3) << 2;
    int tx   = tid & 15, ty = tid >> 4;

    float accg[4][4], accu[4][4];
#pragma unroll
    for (int i = 0; i < 4; i++)
#pragma unroll
        for (int j = 0; j < 4; j++) { accg[i][j] = 0.f; accu[i][j] = 0.f; }

    for (int k0 = 0; k0 < KD; k0 += 16) {
        float4 av;
        if (ROUTED) {
            int tk = stok[lrow];
            if (tk >= 0) av = *(const float4*)(A + (long)tk * KD + k0 + kq);
            else         av = make_float4(0.f, 0.f, 0.f, 0.f);
        } else {
            av = *(const float4*)(A + (long)(r0 + lrow) * KD + k0 + kq);
        }
        float4 gv = *(const float4*)(wg + (long)(n0 + lrow) * KD + k0 + kq);
        float4 uv = *(const float4*)(wu + (long)(n0 + lrow) * KD + k0 + kq);
        As[kq + 0][lrow] = av.x; As[kq + 1][lrow] = av.y; As[kq + 2][lrow] = av.z; As[kq + 3][lrow] = av.w;
        Bg[kq + 0][lrow] = gv.x; Bg[kq + 1][lrow] = gv.y; Bg[kq + 2][lrow] = gv.z; Bg[kq + 3][lrow] = gv.w;
        Bu[kq + 0][lrow] = uv.x; Bu[kq + 1][lrow] = uv.y; Bu[kq + 2][lrow] = uv.z; Bu[kq + 3][lrow] = uv.w;
        __syncthreads();
#pragma unroll
        for (int kk = 0; kk < 16; kk++) {
            float4 a4 = *(const float4*)(&As[kk][ty << 2]);
            float4 g4 = *(const float4*)(&Bg[kk][tx << 2]);
            float4 u4 = *(const float4*)(&Bu[kk][tx << 2]);
            float aa[4] = {a4.x, a4.y, a4.z, a4.w};
            float gg[4] = {g4.x, g4.y, g4.z, g4.w};
            float uu[4] = {u4.x, u4.y, u4.z, u4.w};
#pragma unroll
            for (int i = 0; i < 4; i++)
#pragma unroll
                for (int j = 0; j < 4; j++) {
                    accg[i][j] += aa[i] * gg[j];
                    accu[i][j] += aa[i] * uu[j];
                }
        }
        __syncthreads();
    }

#pragma unroll
    for (int i = 0; i < 4; i++) {
        int rlocal = (ty << 2) + i;
        if (ROUTED && stok[rlocal] < 0) continue;
        long r = r0 + rlocal;
#pragma unroll
        for (int j = 0; j < 4; j++) {
            float g  = accg[i][j];
            float sg = 1.f / (1.f + expf(-g));
            C[r * LDC + n0 + (tx << 2) + j] = g * sg * accu[i][j];
        }
    }
}

// ---------------- down-proj GEMM ----------------------------------------------
// ROUTED: A = g_hbuf (K=IDIM), W per expert [H][I], C = g_ybuf
// !ROUTED: A = g_hsbuf (K=SIDIM), W = shared_down [H][SI], C = out
template <bool ROUTED>
__global__ __launch_bounds__(256) void down_kernel(const float* __restrict__ W,
                                                   float* __restrict__ out)
{
    __shared__ float As[16][68];
    __shared__ float Bs[16][68];
    __shared__ int   stok[64];

    constexpr int KD = ROUTED ? IDIM : SIDIM;
    const float* A = ROUTED ? &g_hbuf[0][0] : &g_hsbuf[0][0];
    float*       C = ROUTED ? &g_ybuf[0][0] : out;

    int tid = threadIdx.x;
    int r0  = blockIdx.y * 64;
    int n0  = blockIdx.x * 64;

    int e = 0;
    if (ROUTED) {
        if (tid < 64) stok[tid] = g_pairtok[r0 + tid];
        __syncthreads();
        if (stok[0] < 0) return;
        e = g_rowexp[r0];
    }
    const float* w = W + (long)e * HDIM * IDIM;

    int lrow = tid >> 2;
    int kq   = (tid & 3) << 2;
    int tx   = tid & 15, ty = tid >> 4;

    float acc[4][4];
#pragma unroll
    for (int i = 0; i < 4; i++)
#pragma unroll
        for (int j = 0; j < 4; j++) acc[i][j] = 0.f;

    for (int k0 = 0; k0 < KD; k0 += 16) {
        float4 av = *(const float4*)(A + (long)(r0 + lrow) * KD + k0 + kq);
        float4 bv = *(const float4*)(w + (long)(n0 + lrow) * KD + k0 + kq);
        As[kq + 0][lrow] = av.x; As[kq + 1][lrow] = av.y; As[kq + 2][lrow] = av.z; As[kq + 3][lrow] = av.w;
        Bs[kq + 0][lrow] = bv.x; Bs[kq + 1][lrow] = bv.y; Bs[kq + 2][lrow] = bv.z; Bs[kq + 3][lrow] = bv.w;
        __syncthreads();
#pragma unroll
        for (int kk = 0; kk < 16; kk++) {
            float4 a4 = *(const float4*)(&As[kk][ty << 2]);
            float4 b4 = *(const float4*)(&Bs[kk][tx << 2]);
            float aa[4] = {a4.x, a4.y, a4.z, a4.w};
            float bb[4] = {b4.x, b4.y, b4.z, b4.w};
#pragma unroll
            for (int i = 0; i < 4; i++)
#pragma unroll
                for (int j = 0; j < 4; j++) acc[i][j] += aa[i] * bb[j];
        }
        __syncthreads();
    }

#pragma unroll
    for (int i = 0; i < 4; i++) {
        int rlocal = (ty << 2) + i;
        if (ROUTED && stok[rlocal] < 0) continue;
        long r = r0 + rlocal;
#pragma unroll
        for (int j = 0; j < 4; j++)
            C[r * HDIM + n0 + (tx << 2) + j] = acc[i][j];
    }
}

// ---------------- combine: out += wmean[e0]*y[p0] + wmean[e1]*y[p1] -----------
__global__ __launch_bounds__(256) void combine_kernel(float* __restrict__ out)
{
    int t  = blockIdx.x;
    int p0 = g_pairof[t][0];
    int p1 = g_pairof[t][1];
    float w0 = g_wmean[g_topi[t][0]];
    float w1 = g_wmean[g_topi[t][1]];
    const float* y0 = g_ybuf[p0];
    const float* y1 = g_ybuf[p1];
    float* o = out + (long)t * HDIM;
    for (int h = threadIdx.x; h < HDIM; h += 256)
        o[h] += w0 * y0[h] + w1 * y1[h];
}

// ---------------- launch -------------------------------------------------------
extern "C" void kernel_launch(void* const* d_in, const int* in_sizes, int n_in,
                              void* d_out, int out_size)
{
    (void)in_sizes; (void)n_in; (void)out_size;
    const float* x   = (const float*)d_in[0];
    const float* gw  = (const float*)d_in[1];
    const float* lb  = (const float*)d_in[2];
    const float* egw = (const float*)d_in[3];
    const float* euw = (const float*)d_in[4];
    const float* edw = (const float*)d_in[5];
    const float* sgw = (const float*)d_in[6];
    const float* suw = (const float*)d_in[7];
    const float* sdw = (const float*)d_in[8];
    float* out = (float*)d_out;

    router_kernel<<<TOK / 8, 256>>>(x, gw, lb);
    stats_kernel<<<NE, 256>>>();
    prefix_kernel<<<1, 1>>>();
    rowmeta_kernel<<<(RMAX + 255) / 256, 256>>>();
    build_kernel<<<(TOK + 255) / 256, 256>>>();

    // routed experts: fused gate/up/silu then down-proj into y buffer
    gateup_kernel<true><<<dim3(IDIM / 64, RMAX / 64), 256>>>(x, egw, euw);
    down_kernel<true><<<dim3(HDIM / 64, RMAX / 64), 256>>>(edw, nullptr);

    // shared expert: gate/up/silu then down-proj straight into out
    gateup_kernel<false><<<dim3(SIDIM / 64, TOK / 64), 256>>>(x, sgw, suw);
    down_kernel<false><<<dim3(HDIM / 64, TOK / 64), 256>>>(sdw, out);

    // add routed contributions
    combine_kernel<<<TOK, 256>>>(out);
}